// round 15
// baseline (speedup 1.0000x reference)
#include <cuda_runtime.h>
#include <cuda_fp16.h>
#include <cstdint>

// ====================== device scratch (no allocs allowed) ======================
__device__ unsigned g_amax_bits;                        // bit pattern of max|W| (monotone, idempotent across replays)
__device__ unsigned g_bar_count;                        // grid-barrier arrivals (reset by last arriver)
__device__ unsigned g_bar_epoch;                        // grid-barrier epoch (monotone across replays)
// B fragments for mma.m16n8k16 (B = f16(A)), t-PAIR packed layout:
// [kstep 0..255][tp 0..1][lane 0..31] -> uint4 { t.b0, t.b1, (t+1).b0, (t+1).b1 }, t = 2*tp
__device__ __align__(16) uint4 g_BfragP[256 * 2 * 32];  // 256 KB (L2-resident)

// ====================== constants ======================
static constexpr int K_DIM  = 4096;
static constexpr int N_OUT  = 12288;
static constexpr int MTILE  = 32;                  // W rows per CTA (2 rowtiles x 16)
static constexpr int NTILES = N_OUT / MTILE;       // 384 (must ALL be co-resident: 3 CTAs/SM x 148 = 444)
static constexpr int KS_PER_SLAB = 8;              // ksteps per B slab
static constexpr int BSLAB  = KS_PER_SLAB * 2 * 32 * 16;  // 8 KB
static constexpr int KS_GRP = 64;                  // ksteps per K-quarter group (1024 k)
static constexpr int NSLABS = KS_GRP / KS_PER_SLAB;       // 8 slabs per group
static constexpr int DSMEM  = 8 * BSLAB;           // 64 KB: 4 groups x double buffer

// ====================== helpers ======================
static __device__ __forceinline__ uint32_t smem_u32(const void* p) {
    uint32_t a;
    asm("{ .reg .u64 t; cvta.to.shared.u64 t, %1; cvt.u32.u64 %0, t; }" : "=r"(a) : "l"(p));
    return a;
}
#define CP_ASYNC16(dst, src) \
    asm volatile("cp.async.cg.shared.global [%0], [%1], 16;" :: "r"(dst), "l"(src))
#define CP_COMMIT() asm volatile("cp.async.commit_group;" ::: "memory")
#define CP_WAIT(n)  asm volatile("cp.async.wait_group %0;" :: "n"(n) : "memory")
#define BAR_SYNC64(id) asm volatile("bar.sync %0, 64;" :: "r"(id) : "memory")

// quantize-dequant pair -> f16x2 of e4m3(RN-sat(w*scale)); lo half = a, hi half = b.
static __device__ __forceinline__ uint32_t qd_pair(float a, float b, float scale) {
    float as = __fmul_rn(a, scale);
    float bs = __fmul_rn(b, scale);
    unsigned short p;
    asm("cvt.rn.satfinite.e4m3x2.f32 %0, %1, %2;" : "=h"(p) : "f"(bs), "f"(as));
    uint32_t r;
    asm("cvt.rn.f16x2.e4m3x2 %0, %1;" : "=r"(r) : "h"(p));
    return r;
}

static __device__ __forceinline__ void mma16816(float* d,
    uint32_t a0, uint32_t a1, uint32_t a2, uint32_t a3, uint32_t b0, uint32_t b1) {
    asm volatile(
        "mma.sync.aligned.m16n8k16.row.col.f32.f16.f16.f32 "
        "{%0,%1,%2,%3}, {%4,%5,%6,%7}, {%8,%9}, {%0,%1,%2,%3};"
        : "+f"(d[0]), "+f"(d[1]), "+f"(d[2]), "+f"(d[3])
        : "r"(a0), "r"(a1), "r"(a2), "r"(a3), "r"(b0), "r"(b1));
}

// ====================== fused persistent kernel: amax (phase 1) + GEMM (phase 2) ======================
// 384 CTAs x 256 threads, ALL co-resident (launch_bounds(256,3), 64 KB smem).
// Phase 1: CTA computes |max| over ITS OWN 32 W rows (-> per-CTA L2 residency for phase 2),
//          CTAs 0..63 also build B fragments. Software grid barrier (epoch + count).
// Phase 2: R14 gemm body: K-split x4, LDG.128+shuffle W quantize, cp.async B slabs.
__global__ void __launch_bounds__(256, 3) k_fused(const float* __restrict__ W,
                                                  const float* __restrict__ A,
                                                  const float* __restrict__ bias,
                                                  float* __restrict__ out) {
    extern __shared__ __align__(16) char bbuf[];    // [group][buf][BSLAB] = 64 KB
    __shared__ float s_red[8];
    __shared__ unsigned s_ab;

    const int tid  = threadIdx.x;
    const int lane = tid & 31;
    const int wid  = tid >> 5;
    const int nb   = blockIdx.x * MTILE;

    // ================= phase 1: amax over this CTA's 32 rows =================
    {
        const float4* ws = (const float4*)(W + (size_t)nb * K_DIM);  // 32768 float4
        float m0 = 0.f, m1 = 0.f, m2 = 0.f, m3 = 0.f;
        #pragma unroll 4
        for (int i = tid; i < MTILE * K_DIM / 4; i += 256) {
            float4 v = ws[i];
            m0 = fmaxf(m0, fabsf(v.x));
            m1 = fmaxf(m1, fabsf(v.y));
            m2 = fmaxf(m2, fabsf(v.z));
            m3 = fmaxf(m3, fabsf(v.w));
        }
        float m = fmaxf(fmaxf(m0, m1), fmaxf(m2, m3));
        #pragma unroll
        for (int o = 16; o; o >>= 1) m = fmaxf(m, __shfl_xor_sync(0xFFFFFFFFu, m, o));
        if (lane == 0) s_red[wid] = m;
        __syncthreads();
        if (tid == 0) {
            float b = s_red[0];
            #pragma unroll
            for (int i = 1; i < 8; ++i) b = fmaxf(b, s_red[i]);
            atomicMax(&g_amax_bits, __float_as_uint(b));
        }
    }

    // ---- B-fragment prep (CTAs 0..63 cover all 16384 entries) ----
    if (blockIdx.x < 64) {
        const int idx = blockIdx.x * 256 + tid;     // [ks 0..255][tp 0..1][lane 0..31]
        const int ln  = idx & 31;
        const int tp  = (idx >> 5) & 1;
        const int ks  = idx >> 6;
        const int r0  = 16 * tp + (ln >> 2);
        const int r1  = r0 + 8;
        const int cc  = ln & 3;
        const int k   = ks * 16;
        const float* Ar0 = A + (size_t)r0 * K_DIM;
        const float* Ar1 = A + (size_t)r1 * K_DIM;
        float2 q00 = *(const float2*)(Ar0 + k + 2 * cc);
        float2 q01 = *(const float2*)(Ar0 + k + 8 + 2 * cc);
        float2 q10 = *(const float2*)(Ar1 + k + 2 * cc);
        float2 q11 = *(const float2*)(Ar1 + k + 8 + 2 * cc);
        auto pack = [](float2 p) -> uint32_t {
            return (uint32_t)__half_as_ushort(__float2half_rn(p.x))
                 | ((uint32_t)__half_as_ushort(__float2half_rn(p.y)) << 16);
        };
        g_BfragP[idx] = make_uint4(pack(q00), pack(q01), pack(q10), pack(q11));
    }

    // ---- prefetch W stage registers BEFORE the barrier (W immutable; hides barrier wait) ----
    const int g    = wid >> 1;                      // K-quarter group 0..3
    const int lw   = wid & 1;                       // rowtile
    const int tig  = tid & 63;                      // thread in group
    const int c    = lane & 3;
    const int perm = 8 * (c & 1) + 4 * (c >> 1);    // {0,8,4,12}
    const bool codd = (c & 1);
    const float4* p0 = (const float4*)(W + (size_t)(nb + 16 * lw + (lane >> 2)) * K_DIM + 1024 * g + perm);
    const float4* p1 = (const float4*)((const float*)p0 + 8 * K_DIM);
    float4 sA[4], sB[4];
    #pragma unroll
    for (int s = 0; s < 4; ++s) {
        sA[s] = __ldg(p0 + 4 * s);
        sB[s] = __ldg(p1 + 4 * s);
    }

    // ================= software grid barrier (all 384 CTAs co-resident) =================
    __syncthreads();
    if (tid == 0) {
        unsigned my_epoch = atomicAdd(&g_bar_epoch, 0u);   // read BEFORE arriving
        __threadfence();                                   // amax atomic + prep STGs visible
        unsigned arrived = atomicAdd(&g_bar_count, 1u);
        if (arrived == NTILES - 1) {
            g_bar_count = 0u;                              // all arrived; safe to reset
            __threadfence();
            atomicAdd(&g_bar_epoch, 1u);
        } else {
            while (atomicAdd(&g_bar_epoch, 0u) == my_epoch) __nanosleep(64);
        }
        s_ab = atomicOr(&g_amax_bits, 0u);                 // L2-coherent read of final amax
    }
    __syncthreads();

    // ================= phase 2: fused quantize + GEMM (R14 body) =================
    const float amax  = fmaxf(__uint_as_float(s_ab), 1e-12f);
    const float scale = __fdiv_rn(448.0f, amax);

    // per-group B double buffer (8 KB slabs of 8 ksteps)
    char* myb0 = bbuf + (size_t)(2 * g) * BSLAB;
    char* myb1 = myb0 + BSLAB;
    const char* bsrc = (const char*)g_BfragP + (size_t)g * (NSLABS * BSLAB);
    {
        uint32_t bd = smem_u32(myb0) + tig * 16;
        #pragma unroll
        for (int i = 0; i < 8; ++i) CP_ASYNC16(bd + i * 1024, bsrc + tig * 16 + i * 1024);
        CP_COMMIT();
    }

    float acc[4][4];
    #pragma unroll
    for (int t = 0; t < 4; ++t)
        #pragma unroll
        for (int i = 0; i < 4; ++i) acc[t][i] = 0.f;

    for (int lc = 0; lc < NSLABS; ++lc) {           // 8 local slabs (8 ksteps each)
        if (lc + 1 < NSLABS) {
            uint32_t bd = smem_u32((lc + 1) & 1 ? myb1 : myb0) + tig * 16;
            const char* bs = bsrc + (size_t)(lc + 1) * BSLAB + tig * 16;
            #pragma unroll
            for (int i = 0; i < 8; ++i) CP_ASYNC16(bd + i * 1024, bs + i * 1024);
            CP_COMMIT();
            CP_WAIT(1);
        } else {
            CP_WAIT(0);
        }
        BAR_SYNC64(g + 1);                          // slab lc visible to group

        const char* bb = (lc & 1) ? myb1 : myb0;
        #pragma unroll
        for (int j = 0; j < KS_PER_SLAB; ++j) {
            const int s = j & 3;
            // quantize stage s -> two f16x2 per row, then shuffle-exchange
            uint32_t u0r = qd_pair(sA[s].x, sA[s].y, scale);
            uint32_t u1r = qd_pair(sA[s].z, sA[s].w, scale);
            uint32_t u0q = qd_pair(sB[s].x, sB[s].y, scale);
            uint32_t u1q = qd_pair(sB[s].z, sB[s].w, scale);
            uint32_t rr = __shfl_xor_sync(0xFFFFFFFFu, codd ? u0r : u1r, 1);
            uint32_t rq = __shfl_xor_sync(0xFFFFFFFFu, codd ? u0q : u1q, 1);
            uint32_t a0 = codd ? rr  : u0r;
            uint32_t a2 = codd ? u1r : rr;
            uint32_t a1 = codd ? rq  : u0q;
            uint32_t a3 = codd ? u1q : rq;
            // reload stage with kstep 4 ahead (clamped; tail loads are redundant L1/L2 hits)
            int ksn = lc * KS_PER_SLAB + j + 4;
            ksn = ksn > KS_GRP - 1 ? KS_GRP - 1 : ksn;
            sA[s] = __ldg(p0 + 4 * ksn);
            sB[s] = __ldg(p1 + 4 * ksn);
            // B t-pair loads (LDS.128) + MMAs
            #pragma unroll
            for (int tp = 0; tp < 2; ++tp) {
                uint4 b = *(const uint4*)(bb + ((j * 2 + tp) * 32 + lane) * 16);
                mma16816(acc[2 * tp],     a0, a1, a2, a3, b.x, b.y);
                mma16816(acc[2 * tp + 1], a0, a1, a2, a3, b.z, b.w);
            }
        }
        BAR_SYNC64(g + 1);                          // group done with slab lc
    }

    // ---- cross-group reduction via smem (reuse bbuf; 16 KB) ----
    __syncthreads();
    float* red = (float*)bbuf;                      // [g][lw][t][i][lane]
    #pragma unroll
    for (int t = 0; t < 4; ++t)
        #pragma unroll
        for (int i = 0; i < 4; ++i)
            red[(((g * 2 + lw) * 4 + t) * 4 + i) * 32 + lane] = acc[t][i];
    __syncthreads();

    // ---- coalesced epilogue: thread -> (A-row ar, 4 consecutive cols) ----
    const float recip = __frcp_rn(scale);
    const int ar = tid >> 3;                        // 0..31
    const int c0 = (tid & 7) * 4;                   // 0..28
    float v[4];
    #pragma unroll
    for (int cc = 0; cc < 4; ++cc) {
        const int col = c0 + cc;
        const int lw2 = col >> 4;
        const int lr  = col & 15;
        const int ln2 = (lr & 7) * 4 + ((ar >> 1) & 3);
        const int i2  = (ar & 1) + 2 * (lr >> 3);
        const int t2  = ar >> 3;
        float s = 0.f;
        #pragma unroll
        for (int g2 = 0; g2 < 4; ++g2)
            s += red[(((g2 * 2 + lw2) * 4 + t2) * 4 + i2) * 32 + ln2];
        v[cc] = s * recip + bias[nb + col];
    }
    *(float4*)(out + (size_t)ar * N_OUT + nb + c0) = make_float4(v[0], v[1], v[2], v[3]);
}

// ====================== launch ======================
extern "C" void kernel_launch(void* const* d_in, const int* in_sizes, int n_in,
                              void* d_out, int out_size) {
    const float* A    = (const float*)d_in[0];   // [32, 4096]
    const float* W    = (const float*)d_in[1];   // [12288, 4096]
    const float* bias = (const float*)d_in[2];   // [12288]
    float* out        = (float*)d_out;           // [32, 12288]

    cudaFuncSetAttribute(k_fused, cudaFuncAttributeMaxDynamicSharedMemorySize, DSMEM);

    k_fused<<<NTILES, 256, DSMEM>>>(W, A, bias, out);
}

// round 16
// speedup vs baseline: 1.2757x; 1.2757x over previous
#include <cuda_runtime.h>
#include <cuda_fp16.h>
#include <cstdint>

// ====================== device scratch (no allocs allowed) ======================
__device__ unsigned g_amax_bits;                        // bit pattern of max|W| (monotone, idempotent across replays)
// B fragments for mma.m16n8k16 (B = f16(A)), t-PAIR packed layout:
// [kstep 0..255][tp 0..1][lane 0..31] -> uint4 { t.b0, t.b1, (t+1).b0, (t+1).b1 }, t = 2*tp
__device__ __align__(16) uint4 g_BfragP[256 * 2 * 32];  // 256 KB (L2-resident)

// ====================== constants ======================
static constexpr int K_DIM  = 4096;
static constexpr int N_OUT  = 12288;
static constexpr int MTILE  = 16;                  // W rows per CTA (1 rowtile)
static constexpr int NTILES = N_OUT / MTILE;       // 768
static constexpr int KSPLIT = 8;                   // K-groups, ONE WARP each (warp-private pipeline)
static constexpr int KS_GRP = 256 / KSPLIT;        // 32 ksteps per group (512 k)
static constexpr int KS_PER_SLAB = 4;              // ksteps per B slab
static constexpr int BSLAB  = KS_PER_SLAB * 2 * 32 * 16;  // 4 KB
static constexpr int NSLABS = KS_GRP / KS_PER_SLAB;       // 8 slabs per group
static constexpr int DSMEM  = KSPLIT * 2 * BSLAB;  // 64 KB (reused for epilogue reduction)

// ====================== helpers ======================
static __device__ __forceinline__ uint32_t smem_u32(const void* p) {
    uint32_t a;
    asm("{ .reg .u64 t; cvta.to.shared.u64 t, %1; cvt.u32.u64 %0, t; }" : "=r"(a) : "l"(p));
    return a;
}
#define CP_ASYNC16(dst, src) \
    asm volatile("cp.async.cg.shared.global [%0], [%1], 16;" :: "r"(dst), "l"(src))
#define CP_COMMIT() asm volatile("cp.async.commit_group;" ::: "memory")
#define CP_WAIT(n)  asm volatile("cp.async.wait_group %0;" :: "n"(n) : "memory")

// quantize-dequant pair -> f16x2 of e4m3(RN-sat(w*scale)); lo half = a, hi half = b.
static __device__ __forceinline__ uint32_t qd_pair(float a, float b, float scale) {
    float as = __fmul_rn(a, scale);
    float bs = __fmul_rn(b, scale);
    unsigned short p;
    asm("cvt.rn.satfinite.e4m3x2.f32 %0, %1, %2;" : "=h"(p) : "f"(bs), "f"(as));
    uint32_t r;
    asm("cvt.rn.f16x2.e4m3x2 %0, %1;" : "=r"(r) : "h"(p));
    return r;
}

static __device__ __forceinline__ void mma16816(float* d,
    uint32_t a0, uint32_t a1, uint32_t a2, uint32_t a3, uint32_t b0, uint32_t b1) {
    asm volatile(
        "mma.sync.aligned.m16n8k16.row.col.f32.f16.f16.f32 "
        "{%0,%1,%2,%3}, {%4,%5,%6,%7}, {%8,%9}, {%0,%1,%2,%3};"
        : "+f"(d[0]), "+f"(d[1]), "+f"(d[2]), "+f"(d[3])
        : "r"(a0), "r"(a1), "r"(a2), "r"(a3), "r"(b0), "r"(b1));
}

// ====================== kernel 1: amax over |W| (+ B-fragment prep in blocks < 64) ======================
__global__ void __launch_bounds__(256) k_amax(const float* __restrict__ W,
                                              const float* __restrict__ A) {
    if (blockIdx.x < 64) {
        const int idx  = blockIdx.x * 256 + threadIdx.x;   // [ks 0..255][tp 0..1][lane 0..31]
        const int lane = idx & 31;
        const int tp   = (idx >> 5) & 1;
        const int ks   = idx >> 6;
        const int r0   = 16 * tp + (lane >> 2);
        const int r1   = r0 + 8;
        const int c    = lane & 3;
        const int k    = ks * 16;

        const float* Ar0 = A + (size_t)r0 * K_DIM;
        const float* Ar1 = A + (size_t)r1 * K_DIM;
        float2 q00 = *(const float2*)(Ar0 + k + 2 * c);
        float2 q01 = *(const float2*)(Ar0 + k + 8 + 2 * c);
        float2 q10 = *(const float2*)(Ar1 + k + 2 * c);
        float2 q11 = *(const float2*)(Ar1 + k + 8 + 2 * c);

        auto pack = [](float2 p) -> uint32_t {
            return (uint32_t)__half_as_ushort(__float2half_rn(p.x))
                 | ((uint32_t)__half_as_ushort(__float2half_rn(p.y)) << 16);
        };
        g_BfragP[idx] = make_uint4(pack(q00), pack(q01), pack(q10), pack(q11));
    }

    __shared__ float red[8];
    const float4* W4 = (const float4*)W;
    const int n4 = (N_OUT * K_DIM) / 4;
    float m0 = 0.f, m1 = 0.f, m2 = 0.f, m3 = 0.f;
    const int stride = gridDim.x * blockDim.x;
    #pragma unroll 4
    for (int i = blockIdx.x * blockDim.x + threadIdx.x; i < n4; i += stride) {
        float4 v = W4[i];
        m0 = fmaxf(m0, fabsf(v.x));
        m1 = fmaxf(m1, fabsf(v.y));
        m2 = fmaxf(m2, fabsf(v.z));
        m3 = fmaxf(m3, fabsf(v.w));
    }
    float m = fmaxf(fmaxf(m0, m1), fmaxf(m2, m3));
    #pragma unroll
    for (int o = 16; o; o >>= 1) m = fmaxf(m, __shfl_xor_sync(0xFFFFFFFFu, m, o));
    if ((threadIdx.x & 31) == 0) red[threadIdx.x >> 5] = m;
    __syncthreads();
    if (threadIdx.x == 0) {
        float b = red[0];
        #pragma unroll
        for (int i = 1; i < 8; ++i) b = fmaxf(b, red[i]);
        atomicMax(&g_amax_bits, __float_as_uint(b));
    }
}

// ====================== kernel 2: fused quantize + GEMM, warp-private K-split x8 ======================
// 768 CTAs x 256 threads, 3 resident CTAs/SM (~24 warps/SM). CTA: 16 W rows x full K.
// Warp w = K-group (k in [512w, 512w+512)) with its OWN double-buffered B slabs:
// producer == consumer warp -> no bar.sync in the mainloop (cp.async wait + syncwarp only).
__global__ void __launch_bounds__(256, 3) k_gemm(const float* __restrict__ W,
                                                 const float* __restrict__ bias,
                                                 float* __restrict__ out) {
    extern __shared__ __align__(16) char bbuf[];    // [warp][buf][BSLAB] = 64 KB

    const int tid  = threadIdx.x;
    const int lane = tid & 31;
    const int g    = tid >> 5;                      // K-group == warp 0..7
    const int nb   = (NTILES - 1 - blockIdx.x) * MTILE;   // reversed tile order (L2 reuse by next amax)

    const float amax  = fmaxf(__uint_as_float(g_amax_bits), 1e-12f);
    const float scale = __fdiv_rn(448.0f, amax);

    // ---- W pointers: LDG.128 per lane, permuted k offset ----
    const int c    = lane & 3;
    const int perm = 8 * (c & 1) + 4 * (c >> 1);    // {0,8,4,12}
    const bool codd = (c & 1);
    const float4* p0 = (const float4*)(W + (size_t)(nb + (lane >> 2)) * K_DIM + 512 * g + perm);
    const float4* p1 = (const float4*)((const float*)p0 + 8 * K_DIM);

    // ---- W register pipeline: 4 kstep stages x 2 float4 ----
    float4 sA[4], sB[4];
    #pragma unroll
    for (int s = 0; s < 4; ++s) {
        sA[s] = __ldg(p0 + 4 * s);
        sB[s] = __ldg(p1 + 4 * s);
    }

    // ---- warp-private B double buffer (4 KB slabs of 4 ksteps) ----
    const uint32_t myb = smem_u32(bbuf) + g * 2 * BSLAB;
    const char* bsrc = (const char*)g_BfragP + (size_t)g * (NSLABS * BSLAB);
    {
        uint32_t bd = myb + lane * 16;              // buffer 0
        const char* bs = bsrc + lane * 16;
        #pragma unroll
        for (int i = 0; i < 8; ++i) CP_ASYNC16(bd + i * 512, bs + i * 512);
        CP_COMMIT();
    }

    float acc[4][4];
    #pragma unroll
    for (int t = 0; t < 4; ++t)
        #pragma unroll
        for (int i = 0; i < 4; ++i) acc[t][i] = 0.f;

    for (int lc = 0; lc < NSLABS; ++lc) {           // 8 warp-local slabs (4 ksteps each)
        if (lc + 1 < NSLABS) {
            uint32_t bd = myb + ((lc + 1) & 1) * BSLAB + lane * 16;
            const char* bs = bsrc + (size_t)(lc + 1) * BSLAB + lane * 16;
            #pragma unroll
            for (int i = 0; i < 8; ++i) CP_ASYNC16(bd + i * 512, bs + i * 512);
            CP_COMMIT();
            CP_WAIT(1);                             // slab lc landed
        } else {
            CP_WAIT(0);
        }
        __syncwarp();                               // cross-lane visibility within the warp

        const char* bb = bbuf + g * 2 * BSLAB + (lc & 1) * BSLAB;
        #pragma unroll
        for (int j = 0; j < KS_PER_SLAB; ++j) {
            const int s = j & 3;
            // quantize stage s -> two f16x2 per row, then shuffle-exchange
            uint32_t u0r = qd_pair(sA[s].x, sA[s].y, scale);
            uint32_t u1r = qd_pair(sA[s].z, sA[s].w, scale);
            uint32_t u0q = qd_pair(sB[s].x, sB[s].y, scale);
            uint32_t u1q = qd_pair(sB[s].z, sB[s].w, scale);
            uint32_t rr = __shfl_xor_sync(0xFFFFFFFFu, codd ? u0r : u1r, 1);
            uint32_t rq = __shfl_xor_sync(0xFFFFFFFFu, codd ? u0q : u1q, 1);
            uint32_t a0 = codd ? rr  : u0r;
            uint32_t a2 = codd ? u1r : rr;
            uint32_t a1 = codd ? rq  : u0q;
            uint32_t a3 = codd ? u1q : rq;
            // reload stage with kstep 4 ahead (clamped; tail loads are redundant L1/L2 hits)
            int ksn = lc * KS_PER_SLAB + j + 4;
            ksn = ksn > KS_GRP - 1 ? KS_GRP - 1 : ksn;
            sA[s] = __ldg(p0 + 4 * ksn);
            sB[s] = __ldg(p1 + 4 * ksn);
            // B t-pair loads (LDS.128) + MMAs
            #pragma unroll
            for (int tp = 0; tp < 2; ++tp) {
                uint4 b = *(const uint4*)(bb + ((j * 2 + tp) * 32 + lane) * 16);
                mma16816(acc[2 * tp],     a0, a1, a2, a3, b.x, b.y);
                mma16816(acc[2 * tp + 1], a0, a1, a2, a3, b.z, b.w);
            }
        }
    }

    // ---- cross-warp reduction via smem (reuse bbuf; 16 KB) ----
    __syncthreads();
    float* red = (float*)bbuf;                      // [g][t][i][lane]
    #pragma unroll
    for (int t = 0; t < 4; ++t)
        #pragma unroll
        for (int i = 0; i < 4; ++i)
            red[((g * 4 + t) * 4 + i) * 32 + lane] = acc[t][i];
    __syncthreads();

    // ---- coalesced epilogue: thread -> (A-row ar, 2 consecutive cols) ----
    const float recip = __frcp_rn(scale);
    const int ar = tid >> 3;                        // 0..31
    const int c0 = (tid & 7) * 2;                   // 0..14
    float v[2];
    #pragma unroll
    for (int cc = 0; cc < 2; ++cc) {
        const int col = c0 + cc;                    // 0..15
        const int ln2 = (col & 7) * 4 + ((ar >> 1) & 3);
        const int i2  = (ar & 1) + 2 * (col >> 3);
        const int t2  = ar >> 3;
        float s = 0.f;
        #pragma unroll
        for (int g2 = 0; g2 < KSPLIT; ++g2)
            s += red[((g2 * 4 + t2) * 4 + i2) * 32 + ln2];
        v[cc] = s * recip + bias[nb + col];
    }
    *(float2*)(out + (size_t)ar * N_OUT + nb + c0) = make_float2(v[0], v[1]);
}

// ====================== launch ======================
extern "C" void kernel_launch(void* const* d_in, const int* in_sizes, int n_in,
                              void* d_out, int out_size) {
    const float* A    = (const float*)d_in[0];   // [32, 4096]
    const float* W    = (const float*)d_in[1];   // [12288, 4096]
    const float* bias = (const float*)d_in[2];   // [12288]
    float* out        = (float*)d_out;           // [32, 12288]

    cudaFuncSetAttribute(k_gemm, cudaFuncAttributeMaxDynamicSharedMemorySize, DSMEM);

    k_amax<<<1184, 256>>>(W, A);
    k_gemm<<<NTILES, 256, DSMEM>>>(W, bias, out);
}